// round 2
// baseline (speedup 1.0000x reference)
#include <cuda_runtime.h>
#include <math.h>

// Problem constants
#define LSEQ   128   // words per sample
#define DIM    768   // bert dim
#define NFEAT  1024  // output features
#define NBATCH 128
#define LOUT   126   // L - 2

// Tiling
#define KC 16        // K-dim chunk
#define TL 64        // positions per CTA
#define TF 64        // features per CTA

// ---------------------------------------------------------------------------
// Kernel 1: fused 3-branch conv (K=2,3,4) + relu + cross-branch max.
// Writes UNNORMALIZED code to out in [b][f][l] layout. Norm over f in kernel 2.
// Grid: (NFEAT/TF, 2, NBATCH). Block: 256 threads (16 f x 16 l),
// each thread computes a 4l x 4f micro-tile for 3 branches (48 accumulators).
// ---------------------------------------------------------------------------
__global__ __launch_bounds__(256, 2)
void conv_kernel(const float* __restrict__ X,
                 const float* __restrict__ W2, const float* __restrict__ b2,
                 const float* __restrict__ W3, const float* __restrict__ b3,
                 const float* __restrict__ W4, const float* __restrict__ b4,
                 float* __restrict__ out)
{
    const int f0 = blockIdx.x * TF;
    const int l0 = blockIdx.y * TL;
    const int b  = blockIdx.z;
    const int tid = threadIdx.x;
    const int tx = tid & 15;   // feature group
    const int ty = tid >> 4;   // position group

    // alignas(16): Ws is read with LDS.128; without explicit alignment the
    // linker may place it at a 4B-aligned offset -> misaligned-address trap.
    __shared__ alignas(16) float Xs[TL + 3][KC + 1];   // 67 x 17 (pad: conflict-free)
    __shared__ alignas(16) float Ws[9][KC][TF];        // 9 slices, d-major

    float accA[4][4] = {};
    float accB[4][4] = {};
    float accC[4][4] = {};

    const float* Xb = X + (size_t)b * LSEQ * DIM;

    for (int ch = 0; ch < DIM / KC; ++ch) {
        const int d0 = ch * KC;
        __syncthreads();

        // Load X tile: (TL+3) rows x KC floats = 268 float4 loads
        #pragma unroll
        for (int m = 0; m < 2; ++m) {
            int idx = tid + m * 256;
            if (idx < (TL + 3) * (KC / 4)) {
                int r = idx >> 2, c = idx & 3;
                int t = l0 + r;
                float4 v = make_float4(0.f, 0.f, 0.f, 0.f);
                if (t < LSEQ) v = *(const float4*)(Xb + (size_t)t * DIM + d0 + c * 4);
                Xs[r][c * 4 + 0] = v.x; Xs[r][c * 4 + 1] = v.y;
                Xs[r][c * 4 + 2] = v.z; Xs[r][c * 4 + 3] = v.w;
            }
        }
        // Load W tiles: 9 slices x TF x KC = 2304 float4 loads (transpose on store)
        #pragma unroll
        for (int m = 0; m < 9; ++m) {
            int idx = tid + m * 256;
            int s   = idx >> 8;
            int rem = idx & 255;
            int f = rem >> 2, c = rem & 3;
            const float* src;
            if (s < 2)      src = W2 + ((size_t)(f0 + f) * 2 + s) * DIM;
            else if (s < 5) src = W3 + ((size_t)(f0 + f) * 3 + (s - 2)) * DIM;
            else            src = W4 + ((size_t)(f0 + f) * 4 + (s - 5)) * DIM;
            float4 v = *(const float4*)(src + d0 + c * 4);
            Ws[s][c * 4 + 0][f] = v.x; Ws[s][c * 4 + 1][f] = v.y;
            Ws[s][c * 4 + 2][f] = v.z; Ws[s][c * 4 + 3][f] = v.w;
        }
        __syncthreads();

        #pragma unroll
        for (int d = 0; d < KC; ++d) {
            float xv[7];
            #pragma unroll
            for (int j = 0; j < 7; ++j) xv[j] = Xs[ty * 4 + j][d];

            float w[9][4];
            #pragma unroll
            for (int s = 0; s < 9; ++s) {
                float4 v = *(const float4*)&Ws[s][d][tx * 4];
                w[s][0] = v.x; w[s][1] = v.y; w[s][2] = v.z; w[s][3] = v.w;
            }
            #pragma unroll
            for (int i = 0; i < 4; ++i) {
                #pragma unroll
                for (int j = 0; j < 4; ++j) {
                    accA[i][j] += xv[i]     * w[0][j] + xv[i + 1] * w[1][j];
                    accB[i][j] += xv[i]     * w[2][j] + xv[i + 1] * w[3][j]
                                + xv[i + 2] * w[4][j];
                    accC[i][j] += xv[i]     * w[5][j] + xv[i + 1] * w[6][j]
                                + xv[i + 2] * w[7][j] + xv[i + 3] * w[8][j];
                }
            }
        }
    }

    // Epilogue: bias + relu + branch-wise max with boundary rules, write [b][f][l]
    #pragma unroll
    for (int i = 0; i < 4; ++i) {
        int l = l0 + ty * 4 + i;
        if (l >= LOUT) continue;
        #pragma unroll
        for (int j = 0; j < 4; ++j) {
            int f = f0 + tx * 4 + j;
            float va = fmaxf(accA[i][j] + b2[f], 0.f);
            float vb = fmaxf(accB[i][j] + b3[f], 0.f);
            float vc = fmaxf(accC[i][j] + b4[f], 0.f);
            float v;
            if (l < LOUT - 2)       v = fmaxf(fmaxf(va, vb), vc);  // l < 124
            else if (l == LOUT - 2) v = fmaxf(va, vb);             // l == 124
            else                    v = va;                        // l == 125
            out[((size_t)b * NFEAT + f) * LOUT + l] = v;
        }
    }
}

// ---------------------------------------------------------------------------
// Kernel 2: l2-normalize code over the feature axis (per (b,l)), in place.
// ---------------------------------------------------------------------------
__global__ void norm_kernel(float* __restrict__ out)
{
    const int b = blockIdx.x;
    float* base = out + (size_t)b * NFEAT * LOUT;
    __shared__ float norms[LOUT];
    const int tid = threadIdx.x;

    if (tid < LOUT) {
        float s = 0.f;
        for (int f = 0; f < NFEAT; ++f) {
            float v = base[(size_t)f * LOUT + tid];
            s += v * v;
        }
        norms[tid] = fmaxf(sqrtf(s), 1e-12f);
    }
    __syncthreads();

    for (int f = 0; f < NFEAT; ++f) {
        for (int l = tid; l < LOUT; l += blockDim.x) {
            base[(size_t)f * LOUT + l] /= norms[l];
        }
    }
}

// ---------------------------------------------------------------------------
// Kernel 3: sentence head: sent = l2norm(sent_emb @ Wp^T + bp).
// ---------------------------------------------------------------------------
__global__ void sent_kernel(const float* __restrict__ S,
                            const float* __restrict__ Wp,
                            const float* __restrict__ bp,
                            float* __restrict__ out)
{
    const int b = blockIdx.x;
    __shared__ float xs[DIM];
    __shared__ float vals[NFEAT];
    __shared__ float red[256];
    const int tid  = threadIdx.x;
    const int warp = tid >> 5, lane = tid & 31;

    for (int i = tid; i < DIM; i += 256) xs[i] = S[(size_t)b * DIM + i];
    __syncthreads();

    for (int f = warp; f < NFEAT; f += 8) {
        const float* w = Wp + (size_t)f * DIM;
        float acc = 0.f;
        #pragma unroll
        for (int d0 = 0; d0 < DIM; d0 += 128) {
            int d = d0 + lane * 4;
            float4 wv = *(const float4*)(w + d);
            acc += xs[d] * wv.x + xs[d + 1] * wv.y + xs[d + 2] * wv.z + xs[d + 3] * wv.w;
        }
        #pragma unroll
        for (int o = 16; o > 0; o >>= 1) acc += __shfl_down_sync(0xffffffffu, acc, o);
        if (lane == 0) vals[f] = acc + bp[f];
    }
    __syncthreads();

    float s = 0.f;
    for (int f = tid; f < NFEAT; f += 256) s += vals[f] * vals[f];
    red[tid] = s;
    __syncthreads();
    for (int o = 128; o > 0; o >>= 1) {
        if (tid < o) red[tid] += red[tid + o];
        __syncthreads();
    }
    float n = fmaxf(sqrtf(red[0]), 1e-12f);

    for (int f = tid; f < NFEAT; f += 256)
        out[(size_t)b * NFEAT + f] = vals[f] / n;
}

// ---------------------------------------------------------------------------
// Launch
// ---------------------------------------------------------------------------
extern "C" void kernel_launch(void* const* d_in, const int* in_sizes, int n_in,
                              void* d_out, int out_size)
{
    const float* X   = (const float*)d_in[0];  // words_emb (128,128,768)
    const float* S   = (const float*)d_in[1];  // sent_emb  (128,768)
    const float* W2  = (const float*)d_in[2];
    const float* b2  = (const float*)d_in[3];
    const float* W3  = (const float*)d_in[4];
    const float* b3  = (const float*)d_in[5];
    const float* W4  = (const float*)d_in[6];
    const float* b4  = (const float*)d_in[7];
    const float* Wp  = (const float*)d_in[8];
    const float* bp  = (const float*)d_in[9];
    float* out = (float*)d_out;

    dim3 grid(NFEAT / TF, 2, NBATCH);   // (16, 2, 128)
    conv_kernel<<<grid, 256>>>(X, W2, b2, W3, b3, W4, b4, out);
    norm_kernel<<<NBATCH, 128>>>(out);
    sent_kernel<<<NBATCH, 256>>>(S, Wp, bp, out + (size_t)NBATCH * NFEAT * LOUT);
}

// round 4
// speedup vs baseline: 2.6476x; 2.6476x over previous
#include <cuda_runtime.h>
#include <cuda_bf16.h>
#include <math.h>
#include <stdint.h>

// ---------------------------------------------------------------------------
// Problem constants
// ---------------------------------------------------------------------------
#define NB    128
#define LSEQ  128
#define DIM   768
#define NF    1024
#define LOUT  126
#define NROWS (NB * LSEQ)

#define K2    1536           // branch kernel=2 flattened K
#define K3    2304
#define K4    3072
#define KTOT  3072
#define KC    32             // K per chunk (bf16 elems)
#define NCHUNK (KTOT / KC)   // 96

// smem layout (bytes)
#define A_STRIDE  80                       // 32 bf16 (64B) + 16B pad, ldmatrix-friendly
#define STAGE_A   (2 * 128 * A_STRIDE)     // hi+lo A: 20480
#define STAGE_B1  (2 * 64 * A_STRIDE)      // hi+lo B per branch: 10240
#define STAGE_SZ  (STAGE_A + 3 * STAGE_B1) // 51200
#define SMEM_DYN  (2 * STAGE_SZ)           // 102400

// ---------------------------------------------------------------------------
// Scratch (device globals; no allocations allowed)
// ---------------------------------------------------------------------------
__device__ __nv_bfloat16 g_Xh[(NROWS + 8) * DIM];
__device__ __nv_bfloat16 g_Xl[(NROWS + 8) * DIM];
#define WTOT (NF * (K2 + K3 + K4))
__device__ __nv_bfloat16 g_Wh[WTOT];
__device__ __nv_bfloat16 g_Wl[WTOT];
__device__ float g_part[NB * 8 * 128];
__device__ float g_rn[NB * 128];

// ---------------------------------------------------------------------------
// Baseline-PTX helpers (all sm_80-class: compile under compute_103)
// ---------------------------------------------------------------------------
static __device__ __forceinline__ uint32_t smem_u32(const void* p) {
    uint32_t a;
    asm("{ .reg .u64 t; cvta.to.shared.u64 t, %1; cvt.u32.u64 %0, t; }"
        : "=r"(a) : "l"(p));
    return a;
}

#define CP_ASYNC16(dst, src) \
    asm volatile("cp.async.cg.shared.global [%0], [%1], 16;" \
                 :: "r"(dst), "l"(src) : "memory")
#define CP_COMMIT() asm volatile("cp.async.commit_group;" ::: "memory")
#define CP_WAIT(n)  asm volatile("cp.async.wait_group %0;" :: "n"(n) : "memory")

#define LDMX4(r, addr) \
    asm volatile("ldmatrix.sync.aligned.m8n8.x4.shared.b16 {%0,%1,%2,%3}, [%4];" \
                 : "=r"((r)[0]), "=r"((r)[1]), "=r"((r)[2]), "=r"((r)[3]) \
                 : "r"(addr))

#define MMA16816(d, a, b0v, b1v) \
    asm volatile("mma.sync.aligned.m16n8k16.row.col.f32.bf16.bf16.f32 " \
                 "{%0,%1,%2,%3},{%4,%5,%6,%7},{%8,%9},{%0,%1,%2,%3};" \
                 : "+f"((d)[0]), "+f"((d)[1]), "+f"((d)[2]), "+f"((d)[3]) \
                 : "r"((a)[0]), "r"((a)[1]), "r"((a)[2]), "r"((a)[3]), \
                   "r"(b0v), "r"(b1v))

// ---------------------------------------------------------------------------
// Prep: fp32 -> bf16 hi/lo splits
// ---------------------------------------------------------------------------
__global__ void cvt_x_kernel(const float* __restrict__ X) {
    const int n = (NROWS + 8) * DIM;
    for (int i = blockIdx.x * blockDim.x + threadIdx.x; i < n; i += gridDim.x * blockDim.x) {
        if (i < NROWS * DIM) {
            float v = X[i];
            __nv_bfloat16 h = __float2bfloat16(v);
            g_Xh[i] = h;
            g_Xl[i] = __float2bfloat16(v - __bfloat162float(h));
        } else {
            g_Xh[i] = __float2bfloat16(0.f);
            g_Xl[i] = __float2bfloat16(0.f);
        }
    }
}

__global__ void cvt_w_kernel(const float* __restrict__ W2, const float* __restrict__ W3,
                             const float* __restrict__ W4) {
    for (int i = blockIdx.x * blockDim.x + threadIdx.x; i < WTOT; i += gridDim.x * blockDim.x) {
        float v;
        if (i < NF * K2)                 v = W2[i];
        else if (i < NF * (K2 + K3))     v = W3[i - NF * K2];
        else                             v = W4[i - NF * (K2 + K3)];
        __nv_bfloat16 h = __float2bfloat16(v);
        g_Wh[i] = h;
        g_Wl[i] = __float2bfloat16(v - __bfloat162float(h));
    }
}

// ---------------------------------------------------------------------------
// Main fused conv kernel (mma.sync bf16, hi/lo 3-combo for fp32 accuracy).
// Grid (16 f-tiles, 128 batches), 256 threads = 8 warps (4 m x 2 n),
// CTA tile 128 pos x 64 feat; warp tile 32x32; 3 branch accumulators.
// ---------------------------------------------------------------------------
__global__ __launch_bounds__(256, 1)
void conv_tc(const float* __restrict__ b2, const float* __restrict__ b3,
             const float* __restrict__ b4, float* __restrict__ out)
{
    extern __shared__ char sm[];
    const uint32_t sb = smem_u32(sm);
    __shared__ float s_bias[3][64];

    const int tid  = threadIdx.x;
    const int lane = tid & 31;
    const int wid  = tid >> 5;
    const int wm   = wid & 3;        // 4 warps along positions
    const int wn   = wid >> 2;       // 2 warps along features
    const int f0   = blockIdx.x * 64;
    const int b    = blockIdx.y;

    if (tid < 64) {
        s_bias[0][tid] = b2[f0 + tid];
        s_bias[1][tid] = b3[f0 + tid];
        s_bias[2][tid] = b4[f0 + tid];
    }

    const int    Ks[3]    = {K2, K3, K4};
    const size_t wbase[3] = {0, (size_t)NF * K2, (size_t)NF * (K2 + K3)};
    const size_t xbase    = (size_t)b * LSEQ * DIM;

    float acc[3][2][4][4];
    #pragma unroll
    for (int bi = 0; bi < 3; ++bi)
        #pragma unroll
        for (int mt = 0; mt < 2; ++mt)
            #pragma unroll
            for (int nt = 0; nt < 4; ++nt)
                #pragma unroll
                for (int q = 0; q < 4; ++q) acc[bi][mt][nt][q] = 0.f;

    // ---- async load of one stage ----
    auto issue_loads = [&](int st, int ch) {
        const int j0 = ch * KC;
        const uint32_t sst = sb + st * STAGE_SZ;
        // A: 2 prec x 128 rows x 4 chunks of 16B  (1024 ops / 256 thr = 4)
        #pragma unroll
        for (int p = 0; p < 4; ++p) {
            int idx  = tid + p * 256;
            int prec = idx >> 9;
            int rem  = idx & 511;
            int row  = rem >> 2, c = rem & 3;
            const __nv_bfloat16* src =
                (prec ? g_Xl : g_Xh) + xbase + (size_t)row * DIM + j0 + c * 8;
            uint32_t dst = sst + prec * (128 * A_STRIDE) + row * A_STRIDE + c * 16;
            CP_ASYNC16(dst, src);
        }
        // B per active branch: 2 prec x 64 rows x 4 chunks (512 ops / 256 = 2)
        #pragma unroll
        for (int bi = 0; bi < 3; ++bi) {
            if (j0 >= Ks[bi]) continue;
            const uint32_t sB = sst + STAGE_A + bi * STAGE_B1;
            #pragma unroll
            for (int p = 0; p < 2; ++p) {
                int idx  = tid + p * 256;
                int prec = idx >> 8;
                int rem  = idx & 255;
                int row  = rem >> 2, c = rem & 3;
                const __nv_bfloat16* src =
                    (prec ? g_Wl : g_Wh) + wbase[bi] + (size_t)(f0 + row) * Ks[bi] + j0 + c * 8;
                uint32_t dst = sB + prec * (64 * A_STRIDE) + row * A_STRIDE + c * 16;
                CP_ASYNC16(dst, src);
            }
        }
        CP_COMMIT();
    };

    issue_loads(0, 0);

    for (int ch = 0; ch < NCHUNK; ++ch) {
        const int j0 = ch * KC;
        if (ch + 1 < NCHUNK) {
            issue_loads((ch + 1) & 1, ch + 1);
            CP_WAIT(1);
        } else {
            CP_WAIT(0);
        }
        __syncthreads();

        const uint32_t sA = sb + (ch & 1) * STAGE_SZ;

        // ---- A fragments: [prec][mt][ks][4] ----
        uint32_t afr[2][2][2][4];
        #pragma unroll
        for (int prec = 0; prec < 2; ++prec)
            #pragma unroll
            for (int mt = 0; mt < 2; ++mt)
                #pragma unroll
                for (int ks = 0; ks < 2; ++ks) {
                    int m = wm * 32 + mt * 16 + (lane & 7) + ((lane >> 3) & 1) * 8;
                    int k = ks * 16 + (lane >> 4) * 8;
                    uint32_t addr = sA + prec * (128 * A_STRIDE) + m * A_STRIDE + k * 2;
                    LDMX4(afr[prec][mt][ks], addr);
                }

        #pragma unroll
        for (int bi = 0; bi < 3; ++bi) {
            if (j0 >= Ks[bi]) continue;
            const uint32_t sB = sA + STAGE_A + bi * STAGE_B1;
            // B fragments: [prec][npair][ks][4] (one x4 = 2 n-tiles, full k16)
            uint32_t bfr[2][2][2][4];
            #pragma unroll
            for (int prec = 0; prec < 2; ++prec)
                #pragma unroll
                for (int np = 0; np < 2; ++np)
                    #pragma unroll
                    for (int ks = 0; ks < 2; ++ks) {
                        int n = wn * 32 + np * 16 + (lane & 7) + (lane >> 4) * 8;
                        int k = ks * 16 + ((lane >> 3) & 1) * 8;
                        uint32_t addr = sB + prec * (64 * A_STRIDE) + n * A_STRIDE + k * 2;
                        LDMX4(bfr[prec][np][ks], addr);
                    }
            // 3 combos: hh, hl, lh
            #pragma unroll
            for (int mt = 0; mt < 2; ++mt)
                #pragma unroll
                for (int np = 0; np < 2; ++np)
                    #pragma unroll
                    for (int sub = 0; sub < 2; ++sub) {
                        const int nt = np * 2 + sub;
                        #pragma unroll
                        for (int ks = 0; ks < 2; ++ks) {
                            MMA16816(acc[bi][mt][nt], afr[0][mt][ks],
                                     bfr[0][np][ks][sub * 2], bfr[0][np][ks][sub * 2 + 1]);
                            MMA16816(acc[bi][mt][nt], afr[0][mt][ks],
                                     bfr[1][np][ks][sub * 2], bfr[1][np][ks][sub * 2 + 1]);
                            MMA16816(acc[bi][mt][nt], afr[1][mt][ks],
                                     bfr[0][np][ks][sub * 2], bfr[0][np][ks][sub * 2 + 1]);
                        }
                    }
        }
        __syncthreads();
    }

    // ---- epilogue: bias+relu+branch max -> smem [64f][132] -> coalesced out ----
    float* sOut = (float*)sm;
    #pragma unroll
    for (int mt = 0; mt < 2; ++mt)
        #pragma unroll
        for (int nt = 0; nt < 4; ++nt) {
            int mb = wm * 32 + mt * 16 + (lane >> 2);
            int n0 = wn * 32 + nt * 8 + (lane & 3) * 2;
            #pragma unroll
            for (int h = 0; h < 2; ++h) {
                int l = mb + h * 8;
                #pragma unroll
                for (int q = 0; q < 2; ++q) {
                    int fl = n0 + q;
                    float va = fmaxf(acc[0][mt][nt][h * 2 + q] + s_bias[0][fl], 0.f);
                    float vb = fmaxf(acc[1][mt][nt][h * 2 + q] + s_bias[1][fl], 0.f);
                    float vc = fmaxf(acc[2][mt][nt][h * 2 + q] + s_bias[2][fl], 0.f);
                    float v;
                    if (l < LOUT - 2)       v = fmaxf(fmaxf(va, vb), vc);
                    else if (l == LOUT - 2) v = fmaxf(va, vb);
                    else                    v = va;     // l >= 126 harmless, not stored
                    sOut[fl * 132 + l] = v;
                }
            }
        }
    __syncthreads();

    for (int idx = tid; idx < 64 * LOUT; idx += 256) {
        int f = idx / LOUT, l = idx % LOUT;
        out[((size_t)b * NF + f0 + f) * LOUT + l] = sOut[f * 132 + l];
    }
}

// ---------------------------------------------------------------------------
// L2-normalize over features: 3 coalesced passes
// ---------------------------------------------------------------------------
__global__ void norm_pass1(const float* __restrict__ out) {
    const int fg = blockIdx.x, b = blockIdx.y;
    const int l = threadIdx.x;
    float s = 0.f;
    if (l < LOUT) {
        const float* base = out + ((size_t)b * NF + fg * 128) * LOUT + l;
        for (int f = 0; f < 128; ++f) {
            float v = base[(size_t)f * LOUT];
            s += v * v;
        }
    }
    g_part[((size_t)b * 8 + fg) * 128 + l] = s;
}

__global__ void norm_pass2() {
    const int b = blockIdx.x, l = threadIdx.x;
    float s = 0.f;
    #pragma unroll
    for (int g = 0; g < 8; ++g) s += g_part[((size_t)b * 8 + g) * 128 + l];
    g_rn[b * 128 + l] = 1.f / fmaxf(sqrtf(s), 1e-12f);
}

__global__ void norm_pass3(float* __restrict__ out) {
    const int n = NB * NF * LOUT;
    for (int i = blockIdx.x * blockDim.x + threadIdx.x; i < n; i += gridDim.x * blockDim.x) {
        int l = i % LOUT;
        int b = i / (NF * LOUT);
        out[i] *= g_rn[b * 128 + l];
    }
}

// ---------------------------------------------------------------------------
// Sentence head
// ---------------------------------------------------------------------------
__global__ void sent_kernel(const float* __restrict__ S, const float* __restrict__ Wp,
                            const float* __restrict__ bp, float* __restrict__ out)
{
    const int b = blockIdx.x;
    __shared__ float xs[DIM];
    __shared__ float vals[NF];
    __shared__ float red[256];
    const int tid = threadIdx.x;
    const int warp = tid >> 5, lane = tid & 31;

    for (int i = tid; i < DIM; i += 256) xs[i] = S[(size_t)b * DIM + i];
    __syncthreads();

    for (int f = warp; f < NF; f += 8) {
        const float* w = Wp + (size_t)f * DIM;
        float acc = 0.f;
        #pragma unroll
        for (int d0 = 0; d0 < DIM; d0 += 128) {
            int d = d0 + lane * 4;
            float4 wv = *(const float4*)(w + d);
            acc += xs[d] * wv.x + xs[d + 1] * wv.y + xs[d + 2] * wv.z + xs[d + 3] * wv.w;
        }
        #pragma unroll
        for (int o = 16; o > 0; o >>= 1) acc += __shfl_down_sync(0xffffffffu, acc, o);
        if (lane == 0) vals[f] = acc + bp[f];
    }
    __syncthreads();

    float s = 0.f;
    for (int f = tid; f < NF; f += 256) s += vals[f] * vals[f];
    red[tid] = s;
    __syncthreads();
    for (int o = 128; o > 0; o >>= 1) {
        if (tid < o) red[tid] += red[tid + o];
        __syncthreads();
    }
    float n = fmaxf(sqrtf(red[0]), 1e-12f);

    for (int f = tid; f < NF; f += 256)
        out[(size_t)b * NF + f] = vals[f] / n;
}

// ---------------------------------------------------------------------------
// Launch
// ---------------------------------------------------------------------------
extern "C" void kernel_launch(void* const* d_in, const int* in_sizes, int n_in,
                              void* d_out, int out_size)
{
    const float* X  = (const float*)d_in[0];
    const float* S  = (const float*)d_in[1];
    const float* W2 = (const float*)d_in[2];
    const float* b2 = (const float*)d_in[3];
    const float* W3 = (const float*)d_in[4];
    const float* b3 = (const float*)d_in[5];
    const float* W4 = (const float*)d_in[6];
    const float* b4 = (const float*)d_in[7];
    const float* Wp = (const float*)d_in[8];
    const float* bp = (const float*)d_in[9];
    float* out = (float*)d_out;

    static int smem_set = 0;
    if (!smem_set) {
        cudaFuncSetAttribute(conv_tc, cudaFuncAttributeMaxDynamicSharedMemorySize, SMEM_DYN);
        smem_set = 1;
    }

    cvt_x_kernel<<<512, 256>>>(X);
    cvt_w_kernel<<<512, 256>>>(W2, W3, W4);
    conv_tc<<<dim3(16, NB), 256, SMEM_DYN>>>(b2, b3, b4, out);
    norm_pass1<<<dim3(8, NB), 128>>>(out);
    norm_pass2<<<NB, 128>>>();
    norm_pass3<<<2048, 256>>>(out);
    sent_kernel<<<NB, 256>>>(S, Wp, bp, out + (size_t)NB * NF * LOUT);
}

// round 5
// speedup vs baseline: 6.1534x; 2.3241x over previous
#include <cuda_runtime.h>
#include <cuda_fp16.h>
#include <math.h>
#include <stdint.h>

// ---------------------------------------------------------------------------
// Problem constants
// ---------------------------------------------------------------------------
#define NB    128
#define LSEQ  128
#define DIM   768
#define NF    1024
#define LOUT  126
#define NROWS (NB * LSEQ)

#define K2    1536           // branch kernel=2 flattened K
#define K3    2304
#define K4    3072
#define KTOT  3072
#define KC    64             // K per chunk (fp16 elems) -> 128B row
#define NCHUNK (KTOT / KC)   // 48

// smem layout (bytes)
#define A_STRIDE  144                      // 64 fp16 (128B) + 16B pad
#define STAGE_A   (128 * A_STRIDE)         // 18432
#define STAGE_B1  (64 * A_STRIDE)          // 9216
#define STAGE_SZ  (STAGE_A + 3 * STAGE_B1) // 46080
#define NSTAGE    3
#define SMEM_DYN  (NSTAGE * STAGE_SZ)      // 138240

// ---------------------------------------------------------------------------
// Scratch (device globals; no allocations allowed)
// ---------------------------------------------------------------------------
__device__ __half g_X[(NROWS + 8) * DIM];
#define WTOT (NF * (K2 + K3 + K4))
__device__ __half g_W[WTOT];
__device__ float g_part[NB * 8 * 128];
__device__ float g_rn[NB * 128];

// ---------------------------------------------------------------------------
// Baseline-PTX helpers (sm_80-class; compile under compute_103)
// ---------------------------------------------------------------------------
static __device__ __forceinline__ uint32_t smem_u32(const void* p) {
    uint32_t a;
    asm("{ .reg .u64 t; cvta.to.shared.u64 t, %1; cvt.u32.u64 %0, t; }"
        : "=r"(a) : "l"(p));
    return a;
}

#define CP_ASYNC16(dst, src) \
    asm volatile("cp.async.cg.shared.global [%0], [%1], 16;" \
                 :: "r"(dst), "l"(src) : "memory")
#define CP_COMMIT() asm volatile("cp.async.commit_group;" ::: "memory")
#define CP_WAIT(n)  asm volatile("cp.async.wait_group %0;" :: "n"(n) : "memory")

#define LDMX4(r, addr) \
    asm volatile("ldmatrix.sync.aligned.m8n8.x4.shared.b16 {%0,%1,%2,%3}, [%4];" \
                 : "=r"((r)[0]), "=r"((r)[1]), "=r"((r)[2]), "=r"((r)[3]) \
                 : "r"(addr))

#define MMA16816(d, a, b0v, b1v) \
    asm volatile("mma.sync.aligned.m16n8k16.row.col.f32.f16.f16.f32 " \
                 "{%0,%1,%2,%3},{%4,%5,%6,%7},{%8,%9},{%0,%1,%2,%3};" \
                 : "+f"((d)[0]), "+f"((d)[1]), "+f"((d)[2]), "+f"((d)[3]) \
                 : "r"((a)[0]), "r"((a)[1]), "r"((a)[2]), "r"((a)[3]), \
                   "r"(b0v), "r"(b1v))

// ---------------------------------------------------------------------------
// Prep: fp32 -> fp16 (single precision pass; error budget ~4e-4 global)
// ---------------------------------------------------------------------------
__global__ void cvt_x_kernel(const float* __restrict__ X) {
    const int n2 = (NROWS + 8) * DIM / 2;
    const int lim2 = NROWS * DIM / 2;
    __half2* dst = (__half2*)g_X;
    for (int i = blockIdx.x * blockDim.x + threadIdx.x; i < n2; i += gridDim.x * blockDim.x) {
        float2 v = (i < lim2) ? *(const float2*)(X + 2 * i) : make_float2(0.f, 0.f);
        dst[i] = __floats2half2_rn(v.x, v.y);
    }
}

__global__ void cvt_w_kernel(const float* __restrict__ W2, const float* __restrict__ W3,
                             const float* __restrict__ W4) {
    const int n2 = WTOT / 2;
    __half2* dst = (__half2*)g_W;
    for (int i = blockIdx.x * blockDim.x + threadIdx.x; i < n2; i += gridDim.x * blockDim.x) {
        int j = 2 * i;
        const float* src;
        if (j < NF * K2)             src = W2 + j;
        else if (j < NF * (K2 + K3)) src = W3 + (j - NF * K2);
        else                         src = W4 + (j - NF * (K2 + K3));
        float2 v = *(const float2*)src;
        dst[i] = __floats2half2_rn(v.x, v.y);
    }
}

// ---------------------------------------------------------------------------
// Fused conv (3 overlapping GEMMs), fp16 mma.sync, fp32 accum.
// Grid (16 f-tiles, 128 batches), 256 threads = 8 warps (4 m x 2 n),
// CTA tile 128 pos x 64 feat, warp tile 32x32; KC=64; 3-stage cp.async.
// ---------------------------------------------------------------------------
__global__ __launch_bounds__(256, 1)
void conv_tc(const float* __restrict__ b2, const float* __restrict__ b3,
             const float* __restrict__ b4, float* __restrict__ out)
{
    extern __shared__ char sm[];
    const uint32_t sb = smem_u32(sm);
    __shared__ float s_bias[3][64];

    const int tid  = threadIdx.x;
    const int lane = tid & 31;
    const int wid  = tid >> 5;
    const int wm   = wid & 3;
    const int wn   = wid >> 2;
    const int f0   = blockIdx.x * 64;
    const int b    = blockIdx.y;

    if (tid < 64) {
        s_bias[0][tid] = b2[f0 + tid];
        s_bias[1][tid] = b3[f0 + tid];
        s_bias[2][tid] = b4[f0 + tid];
    }

    const int    Ks[3]    = {K2, K3, K4};
    const size_t wbase[3] = {0, (size_t)NF * K2, (size_t)NF * (K2 + K3)};
    const size_t xbase    = (size_t)b * LSEQ * DIM;

    float acc[3][2][4][4];
    #pragma unroll
    for (int bi = 0; bi < 3; ++bi)
        #pragma unroll
        for (int mt = 0; mt < 2; ++mt)
            #pragma unroll
            for (int nt = 0; nt < 4; ++nt)
                #pragma unroll
                for (int q = 0; q < 4; ++q) acc[bi][mt][nt][q] = 0.f;

    auto issue_loads = [&](int st, int ch) {
        const int j0 = ch * KC;
        const uint32_t sst = sb + st * STAGE_SZ;
        // A: 128 rows x 8 x 16B = 1024 ops / 256 thr = 4
        #pragma unroll
        for (int p = 0; p < 4; ++p) {
            int idx = tid + p * 256;
            int row = idx >> 3, c = idx & 7;
            const __half* src = g_X + xbase + (size_t)row * DIM + j0 + c * 8;
            CP_ASYNC16(sst + row * A_STRIDE + c * 16, src);
        }
        // B per active branch: 64 rows x 8 = 512 / 256 = 2
        #pragma unroll
        for (int bi = 0; bi < 3; ++bi) {
            if (j0 >= Ks[bi]) continue;
            const uint32_t sB = sst + STAGE_A + bi * STAGE_B1;
            #pragma unroll
            for (int p = 0; p < 2; ++p) {
                int idx = tid + p * 256;
                int row = idx >> 3, c = idx & 7;
                const __half* src = g_W + wbase[bi] + (size_t)(f0 + row) * Ks[bi] + j0 + c * 8;
                CP_ASYNC16(sB + row * A_STRIDE + c * 16, src);
            }
        }
        CP_COMMIT();
    };

    issue_loads(0, 0);
    issue_loads(1, 1);

    for (int ch = 0; ch < NCHUNK; ++ch) {
        const int j0 = ch * KC;
        if (ch + 2 < NCHUNK) { issue_loads((ch + 2) % NSTAGE, ch + 2); CP_WAIT(2); }
        else if (ch + 1 < NCHUNK) { CP_WAIT(1); }
        else { CP_WAIT(0); }
        __syncthreads();

        const uint32_t sA = sb + (ch % NSTAGE) * STAGE_SZ;

        // A fragments [mt][ks][4]: 16x16 tiles, 4 k-steps of KC=64
        uint32_t afr[2][4][4];
        #pragma unroll
        for (int mt = 0; mt < 2; ++mt)
            #pragma unroll
            for (int ks = 0; ks < 4; ++ks) {
                int m = wm * 32 + mt * 16 + (lane & 7) + ((lane >> 3) & 1) * 8;
                int k = ks * 16 + (lane >> 4) * 8;
                LDMX4(afr[mt][ks], sA + m * A_STRIDE + k * 2);
            }

        #pragma unroll
        for (int bi = 0; bi < 3; ++bi) {
            if (j0 >= Ks[bi]) continue;
            const uint32_t sB = sA + STAGE_A + bi * STAGE_B1;
            uint32_t bfr[2][4][4];
            #pragma unroll
            for (int np = 0; np < 2; ++np)
                #pragma unroll
                for (int ks = 0; ks < 4; ++ks) {
                    int n = wn * 32 + np * 16 + (lane & 7) + (lane >> 4) * 8;
                    int k = ks * 16 + ((lane >> 3) & 1) * 8;
                    LDMX4(bfr[np][ks], sB + n * A_STRIDE + k * 2);
                }
            #pragma unroll
            for (int mt = 0; mt < 2; ++mt)
                #pragma unroll
                for (int np = 0; np < 2; ++np)
                    #pragma unroll
                    for (int sub = 0; sub < 2; ++sub) {
                        const int nt = np * 2 + sub;
                        #pragma unroll
                        for (int ks = 0; ks < 4; ++ks)
                            MMA16816(acc[bi][mt][nt], afr[mt][ks],
                                     bfr[np][ks][sub * 2], bfr[np][ks][sub * 2 + 1]);
                    }
        }
        __syncthreads();
    }

    // ---- epilogue: bias+relu+branch max -> smem [64f][132] -> coalesced out ----
    float* sOut = (float*)sm;
    #pragma unroll
    for (int mt = 0; mt < 2; ++mt)
        #pragma unroll
        for (int nt = 0; nt < 4; ++nt) {
            int mb = wm * 32 + mt * 16 + (lane >> 2);
            int n0 = wn * 32 + nt * 8 + (lane & 3) * 2;
            #pragma unroll
            for (int h = 0; h < 2; ++h) {
                int l = mb + h * 8;
                #pragma unroll
                for (int q = 0; q < 2; ++q) {
                    int fl = n0 + q;
                    float va = fmaxf(acc[0][mt][nt][h * 2 + q] + s_bias[0][fl], 0.f);
                    float vb = fmaxf(acc[1][mt][nt][h * 2 + q] + s_bias[1][fl], 0.f);
                    float vc = fmaxf(acc[2][mt][nt][h * 2 + q] + s_bias[2][fl], 0.f);
                    float v;
                    if (l < LOUT - 2)       v = fmaxf(fmaxf(va, vb), vc);
                    else if (l == LOUT - 2) v = fmaxf(va, vb);
                    else                    v = va;     // l >= 126 not stored
                    sOut[fl * 132 + l] = v;
                }
            }
        }
    __syncthreads();

    for (int idx = tid; idx < 64 * LOUT; idx += 256) {
        int f = idx / LOUT, l = idx % LOUT;
        out[((size_t)b * NF + f0 + f) * LOUT + l] = sOut[f * 132 + l];
    }
}

// ---------------------------------------------------------------------------
// L2-normalize over features: 3 coalesced passes
// ---------------------------------------------------------------------------
__global__ void norm_pass1(const float* __restrict__ out) {
    const int fg = blockIdx.x, b = blockIdx.y;
    const int l = threadIdx.x;
    float s = 0.f;
    if (l < LOUT) {
        const float* base = out + ((size_t)b * NF + fg * 128) * LOUT + l;
        for (int f = 0; f < 128; ++f) {
            float v = base[(size_t)f * LOUT];
            s += v * v;
        }
    }
    g_part[((size_t)b * 8 + fg) * 128 + l] = s;
}

__global__ void norm_pass2() {
    const int b = blockIdx.x, l = threadIdx.x;
    float s = 0.f;
    #pragma unroll
    for (int g = 0; g < 8; ++g) s += g_part[((size_t)b * 8 + g) * 128 + l];
    g_rn[b * 128 + l] = 1.f / fmaxf(sqrtf(s), 1e-12f);
}

__global__ void norm_pass3(float* __restrict__ out) {
    const int n = NB * NF * LOUT;
    for (int i = blockIdx.x * blockDim.x + threadIdx.x; i < n; i += gridDim.x * blockDim.x) {
        int l = i % LOUT;
        int b = i / (NF * LOUT);
        out[i] *= g_rn[b * 128 + l];
    }
}

// ---------------------------------------------------------------------------
// Sentence head
// ---------------------------------------------------------------------------
__global__ void sent_kernel(const float* __restrict__ S, const float* __restrict__ Wp,
                            const float* __restrict__ bp, float* __restrict__ out)
{
    const int b = blockIdx.x;
    __shared__ float xs[DIM];
    __shared__ float vals[NF];
    __shared__ float red[256];
    const int tid = threadIdx.x;
    const int warp = tid >> 5, lane = tid & 31;

    for (int i = tid; i < DIM; i += 256) xs[i] = S[(size_t)b * DIM + i];
    __syncthreads();

    for (int f = warp; f < NF; f += 8) {
        const float* w = Wp + (size_t)f * DIM;
        float acc = 0.f;
        #pragma unroll
        for (int d0 = 0; d0 < DIM; d0 += 128) {
            int d = d0 + lane * 4;
            float4 wv = *(const float4*)(w + d);
            acc += xs[d] * wv.x + xs[d + 1] * wv.y + xs[d + 2] * wv.z + xs[d + 3] * wv.w;
        }
        #pragma unroll
        for (int o = 16; o > 0; o >>= 1) acc += __shfl_down_sync(0xffffffffu, acc, o);
        if (lane == 0) vals[f] = acc + bp[f];
    }
    __syncthreads();

    float s = 0.f;
    for (int f = tid; f < NF; f += 256) s += vals[f] * vals[f];
    red[tid] = s;
    __syncthreads();
    for (int o = 128; o > 0; o >>= 1) {
        if (tid < o) red[tid] += red[tid + o];
        __syncthreads();
    }
    float n = fmaxf(sqrtf(red[0]), 1e-12f);

    for (int f = tid; f < NF; f += 256)
        out[(size_t)b * NF + f] = vals[f] / n;
}

// ---------------------------------------------------------------------------
// Launch
// ---------------------------------------------------------------------------
extern "C" void kernel_launch(void* const* d_in, const int* in_sizes, int n_in,
                              void* d_out, int out_size)
{
    const float* X  = (const float*)d_in[0];
    const float* S  = (const float*)d_in[1];
    const float* W2 = (const float*)d_in[2];
    const float* b2 = (const float*)d_in[3];
    const float* W3 = (const float*)d_in[4];
    const float* b3 = (const float*)d_in[5];
    const float* W4 = (const float*)d_in[6];
    const float* b4 = (const float*)d_in[7];
    const float* Wp = (const float*)d_in[8];
    const float* bp = (const float*)d_in[9];
    float* out = (float*)d_out;

    static int smem_set = 0;
    if (!smem_set) {
        cudaFuncSetAttribute(conv_tc, cudaFuncAttributeMaxDynamicSharedMemorySize, SMEM_DYN);
        smem_set = 1;
    }

    cvt_x_kernel<<<1024, 256>>>(X);
    cvt_w_kernel<<<1024, 256>>>(W2, W3, W4);
    conv_tc<<<dim3(16, NB), 256, SMEM_DYN>>>(b2, b3, b4, out);
    norm_pass1<<<dim3(8, NB), 128>>>(out);
    norm_pass2<<<NB, 128>>>();
    norm_pass3<<<2048, 256>>>(out);
    sent_kernel<<<NB, 256>>>(S, Wp, bp, out + (size_t)NB * NF * LOUT);
}

// round 6
// speedup vs baseline: 6.8389x; 1.1114x over previous
#include <cuda_runtime.h>
#include <cuda_fp16.h>
#include <math.h>
#include <stdint.h>

// ---------------------------------------------------------------------------
// Problem constants
// ---------------------------------------------------------------------------
#define NB    128
#define LSEQ  128
#define DIM   768
#define NF    1024
#define LOUT  126
#define NROWS (NB * LSEQ)

#define K2    1536           // branch kernel=2 flattened K
#define K3    2304
#define K4    3072
#define KTOT  3072
#define KC    64             // K per chunk (fp16 elems) -> 128B row
#define NCHUNK (KTOT / KC)   // 48

// smem layout (bytes)
#define A_STRIDE  144                      // 64 fp16 (128B) + 16B pad
#define STAGE_A   (128 * A_STRIDE)         // 18432
#define STAGE_B1  (64 * A_STRIDE)          // 9216
#define STAGE_SZ  (STAGE_A + 3 * STAGE_B1) // 46080
#define NSTAGE    4
#define SMEM_DYN  (NSTAGE * STAGE_SZ)      // 184320

// ---------------------------------------------------------------------------
// Scratch (device globals; no allocations allowed)
// ---------------------------------------------------------------------------
__device__ __half g_X[(NROWS + 8) * DIM];
#define WTOT (NF * (K2 + K3 + K4))
__device__ __half g_W[WTOT];
__device__ float g_part[NB * 8 * 128];
__device__ float g_rn[NB * 128];

// ---------------------------------------------------------------------------
// Baseline-PTX helpers (sm_80-class; compile under compute_103)
// ---------------------------------------------------------------------------
static __device__ __forceinline__ uint32_t smem_u32(const void* p) {
    uint32_t a;
    asm("{ .reg .u64 t; cvta.to.shared.u64 t, %1; cvt.u32.u64 %0, t; }"
        : "=r"(a) : "l"(p));
    return a;
}

#define CP_ASYNC16(dst, src) \
    asm volatile("cp.async.cg.shared.global [%0], [%1], 16;" \
                 :: "r"(dst), "l"(src) : "memory")
#define CP_COMMIT() asm volatile("cp.async.commit_group;" ::: "memory")
#define CP_WAIT(n)  asm volatile("cp.async.wait_group %0;" :: "n"(n) : "memory")

#define LDMX4(r, addr) \
    asm volatile("ldmatrix.sync.aligned.m8n8.x4.shared.b16 {%0,%1,%2,%3}, [%4];" \
                 : "=r"((r)[0]), "=r"((r)[1]), "=r"((r)[2]), "=r"((r)[3]) \
                 : "r"(addr))

#define MMA16816(d, a, b0v, b1v) \
    asm volatile("mma.sync.aligned.m16n8k16.row.col.f32.f16.f16.f32 " \
                 "{%0,%1,%2,%3},{%4,%5,%6,%7},{%8,%9},{%0,%1,%2,%3};" \
                 : "+f"((d)[0]), "+f"((d)[1]), "+f"((d)[2]), "+f"((d)[3]) \
                 : "r"((a)[0]), "r"((a)[1]), "r"((a)[2]), "r"((a)[3]), \
                   "r"(b0v), "r"(b1v))

// ---------------------------------------------------------------------------
// Prep: fp32 -> fp16
// ---------------------------------------------------------------------------
__global__ void cvt_x_kernel(const float* __restrict__ X) {
    const int n2 = (NROWS + 8) * DIM / 2;
    const int lim2 = NROWS * DIM / 2;
    __half2* dst = (__half2*)g_X;
    for (int i = blockIdx.x * blockDim.x + threadIdx.x; i < n2; i += gridDim.x * blockDim.x) {
        float2 v = (i < lim2) ? *(const float2*)(X + 2 * i) : make_float2(0.f, 0.f);
        dst[i] = __floats2half2_rn(v.x, v.y);
    }
}

__global__ void cvt_w_kernel(const float* __restrict__ W2, const float* __restrict__ W3,
                             const float* __restrict__ W4) {
    const int n2 = WTOT / 2;
    __half2* dst = (__half2*)g_W;
    for (int i = blockIdx.x * blockDim.x + threadIdx.x; i < n2; i += gridDim.x * blockDim.x) {
        int j = 2 * i;
        const float* src;
        if (j < NF * K2)             src = W2 + j;
        else if (j < NF * (K2 + K3)) src = W3 + (j - NF * K2);
        else                         src = W4 + (j - NF * (K2 + K3));
        float2 v = *(const float2*)src;
        dst[i] = __floats2half2_rn(v.x, v.y);
    }
}

// ---------------------------------------------------------------------------
// Fused conv (3 overlapping GEMMs), fp16 mma.sync, fp32 accum.
// Grid (16 f-tiles, 128 batches), 256 threads = 8 warps (4 m x 2 n),
// CTA tile 128 pos x 64 feat, warp tile 32x32; KC=64;
// 4-stage cp.async pipeline, ONE barrier per chunk.
// ---------------------------------------------------------------------------
__global__ __launch_bounds__(256, 1)
void conv_tc(const float* __restrict__ b2, const float* __restrict__ b3,
             const float* __restrict__ b4, float* __restrict__ out)
{
    extern __shared__ char sm[];
    const uint32_t sb = smem_u32(sm);
    __shared__ float s_bias[3][64];

    const int tid  = threadIdx.x;
    const int lane = tid & 31;
    const int wid  = tid >> 5;
    const int wm   = wid & 3;
    const int wn   = wid >> 2;
    const int f0   = blockIdx.x * 64;
    const int b    = blockIdx.y;

    if (tid < 64) {
        s_bias[0][tid] = b2[f0 + tid];
        s_bias[1][tid] = b3[f0 + tid];
        s_bias[2][tid] = b4[f0 + tid];
    }

    const int    Ks[3]    = {K2, K3, K4};
    const size_t wbase[3] = {0, (size_t)NF * K2, (size_t)NF * (K2 + K3)};
    const size_t xbase    = (size_t)b * LSEQ * DIM;

    float acc[3][2][4][4];
    #pragma unroll
    for (int bi = 0; bi < 3; ++bi)
        #pragma unroll
        for (int mt = 0; mt < 2; ++mt)
            #pragma unroll
            for (int nt = 0; nt < 4; ++nt)
                #pragma unroll
                for (int q = 0; q < 4; ++q) acc[bi][mt][nt][q] = 0.f;

    auto issue_loads = [&](int st, int ch) {
        const int j0 = ch * KC;
        const uint32_t sst = sb + st * STAGE_SZ;
        // A: 128 rows x 8 x 16B = 1024 ops / 256 thr = 4
        #pragma unroll
        for (int p = 0; p < 4; ++p) {
            int idx = tid + p * 256;
            int row = idx >> 3, c = idx & 7;
            const __half* src = g_X + xbase + (size_t)row * DIM + j0 + c * 8;
            CP_ASYNC16(sst + row * A_STRIDE + c * 16, src);
        }
        // B per active branch: 64 rows x 8 = 512 / 256 = 2
        #pragma unroll
        for (int bi = 0; bi < 3; ++bi) {
            if (j0 >= Ks[bi]) continue;
            const uint32_t sB = sst + STAGE_A + bi * STAGE_B1;
            #pragma unroll
            for (int p = 0; p < 2; ++p) {
                int idx = tid + p * 256;
                int row = idx >> 3, c = idx & 7;
                const __half* src = g_W + wbase[bi] + (size_t)(f0 + row) * Ks[bi] + j0 + c * 8;
                CP_ASYNC16(sB + row * A_STRIDE + c * 16, src);
            }
        }
        CP_COMMIT();
    };

    issue_loads(0, 0);
    issue_loads(1, 1);

    for (int ch = 0; ch < NCHUNK; ++ch) {
        const int j0 = ch * KC;
        // Issue ch+2 into stage (ch+2)%4. Worst-case lagging reader is at
        // iter ch-1 on stage (ch-1)%4; (ch+2)-(ch-1)=3 != 0 mod 4 -> no
        // conflict, so NO trailing barrier is needed (single sync per chunk).
        if (ch + 2 < NCHUNK) { issue_loads((ch + 2) % NSTAGE, ch + 2); CP_WAIT(2); }
        else if (ch + 1 < NCHUNK) { CP_WAIT(1); }
        else { CP_WAIT(0); }
        __syncthreads();

        const uint32_t sA = sb + (ch % NSTAGE) * STAGE_SZ;

        // A fragments [mt][ks][4]: 16x16 tiles, 4 k-steps of KC=64
        uint32_t afr[2][4][4];
        #pragma unroll
        for (int mt = 0; mt < 2; ++mt)
            #pragma unroll
            for (int ks = 0; ks < 4; ++ks) {
                int m = wm * 32 + mt * 16 + (lane & 7) + ((lane >> 3) & 1) * 8;
                int k = ks * 16 + (lane >> 4) * 8;
                LDMX4(afr[mt][ks], sA + m * A_STRIDE + k * 2);
            }

        #pragma unroll
        for (int bi = 0; bi < 3; ++bi) {
            if (j0 >= Ks[bi]) continue;
            const uint32_t sB = sA + STAGE_A + bi * STAGE_B1;
            uint32_t bfr[2][4][4];
            #pragma unroll
            for (int np = 0; np < 2; ++np)
                #pragma unroll
                for (int ks = 0; ks < 4; ++ks) {
                    int n = wn * 32 + np * 16 + (lane & 7) + (lane >> 4) * 8;
                    int k = ks * 16 + ((lane >> 3) & 1) * 8;
                    LDMX4(bfr[np][ks], sB + n * A_STRIDE + k * 2);
                }
            #pragma unroll
            for (int mt = 0; mt < 2; ++mt)
                #pragma unroll
                for (int np = 0; np < 2; ++np)
                    #pragma unroll
                    for (int sub = 0; sub < 2; ++sub) {
                        const int nt = np * 2 + sub;
                        #pragma unroll
                        for (int ks = 0; ks < 4; ++ks)
                            MMA16816(acc[bi][mt][nt], afr[mt][ks],
                                     bfr[np][ks][sub * 2], bfr[np][ks][sub * 2 + 1]);
                    }
        }
        // no trailing __syncthreads (4-stage ring makes it unnecessary)
    }

    // ---- epilogue: bias+relu+branch max -> smem [64f][132] -> coalesced out ----
    // sOut occupies [0, 33792) = inside stage 0; lagging warps can only be in
    // chunk 47 (stage 3, offset 138240+) -> no overlap.
    float* sOut = (float*)sm;
    #pragma unroll
    for (int mt = 0; mt < 2; ++mt)
        #pragma unroll
        for (int nt = 0; nt < 4; ++nt) {
            int mb = wm * 32 + mt * 16 + (lane >> 2);
            int n0 = wn * 32 + nt * 8 + (lane & 3) * 2;
            #pragma unroll
            for (int h = 0; h < 2; ++h) {
                int l = mb + h * 8;
                #pragma unroll
                for (int q = 0; q < 2; ++q) {
                    int fl = n0 + q;
                    float va = fmaxf(acc[0][mt][nt][h * 2 + q] + s_bias[0][fl], 0.f);
                    float vb = fmaxf(acc[1][mt][nt][h * 2 + q] + s_bias[1][fl], 0.f);
                    float vc = fmaxf(acc[2][mt][nt][h * 2 + q] + s_bias[2][fl], 0.f);
                    float v;
                    if (l < LOUT - 2)       v = fmaxf(fmaxf(va, vb), vc);
                    else if (l == LOUT - 2) v = fmaxf(va, vb);
                    else                    v = va;     // l >= 126 not stored
                    sOut[fl * 132 + l] = v;
                }
            }
        }
    __syncthreads();

    for (int idx = tid; idx < 64 * LOUT; idx += 256) {
        int f = idx / LOUT, l = idx % LOUT;
        out[((size_t)b * NF + f0 + f) * LOUT + l] = sOut[f * 132 + l];
    }
}

// ---------------------------------------------------------------------------
// L2-normalize over features: 3 coalesced passes
// ---------------------------------------------------------------------------
__global__ void norm_pass1(const float* __restrict__ out) {
    const int fg = blockIdx.x, b = blockIdx.y;
    const int l = threadIdx.x;
    float s = 0.f;
    if (l < LOUT) {
        const float* base = out + ((size_t)b * NF + fg * 128) * LOUT + l;
        for (int f = 0; f < 128; ++f) {
            float v = base[(size_t)f * LOUT];
            s += v * v;
        }
    }
    g_part[((size_t)b * 8 + fg) * 128 + l] = s;
}

__global__ void norm_pass2() {
    const int b = blockIdx.x, l = threadIdx.x;
    float s = 0.f;
    #pragma unroll
    for (int g = 0; g < 8; ++g) s += g_part[((size_t)b * 8 + g) * 128 + l];
    g_rn[b * 128 + l] = 1.f / fmaxf(sqrtf(s), 1e-12f);
}

__global__ void norm_pass3(float* __restrict__ out) {
    const int n = NB * NF * LOUT;
    for (int i = blockIdx.x * blockDim.x + threadIdx.x; i < n; i += gridDim.x * blockDim.x) {
        int l = i % LOUT;
        int b = i / (NF * LOUT);
        out[i] *= g_rn[b * 128 + l];
    }
}

// ---------------------------------------------------------------------------
// Sentence head
// ---------------------------------------------------------------------------
__global__ void sent_kernel(const float* __restrict__ S, const float* __restrict__ Wp,
                            const float* __restrict__ bp, float* __restrict__ out)
{
    const int b = blockIdx.x;
    __shared__ float xs[DIM];
    __shared__ float vals[NF];
    __shared__ float red[256];
    const int tid = threadIdx.x;
    const int warp = tid >> 5, lane = tid & 31;

    for (int i = tid; i < DIM; i += 256) xs[i] = S[(size_t)b * DIM + i];
    __syncthreads();

    for (int f = warp; f < NF; f += 8) {
        const float* w = Wp + (size_t)f * DIM;
        float acc = 0.f;
        #pragma unroll
        for (int d0 = 0; d0 < DIM; d0 += 128) {
            int d = d0 + lane * 4;
            float4 wv = *(const float4*)(w + d);
            acc += xs[d] * wv.x + xs[d + 1] * wv.y + xs[d + 2] * wv.z + xs[d + 3] * wv.w;
        }
        #pragma unroll
        for (int o = 16; o > 0; o >>= 1) acc += __shfl_down_sync(0xffffffffu, acc, o);
        if (lane == 0) vals[f] = acc + bp[f];
    }
    __syncthreads();

    float s = 0.f;
    for (int f = tid; f < NF; f += 256) s += vals[f] * vals[f];
    red[tid] = s;
    __syncthreads();
    for (int o = 128; o > 0; o >>= 1) {
        if (tid < o) red[tid] += red[tid + o];
        __syncthreads();
    }
    float n = fmaxf(sqrtf(red[0]), 1e-12f);

    for (int f = tid; f < NF; f += 256)
        out[(size_t)b * NF + f] = vals[f] / n;
}

// ---------------------------------------------------------------------------
// Launch
// ---------------------------------------------------------------------------
extern "C" void kernel_launch(void* const* d_in, const int* in_sizes, int n_in,
                              void* d_out, int out_size)
{
    const float* X  = (const float*)d_in[0];
    const float* S  = (const float*)d_in[1];
    const float* W2 = (const float*)d_in[2];
    const float* b2 = (const float*)d_in[3];
    const float* W3 = (const float*)d_in[4];
    const float* b3 = (const float*)d_in[5];
    const float* W4 = (const float*)d_in[6];
    const float* b4 = (const float*)d_in[7];
    const float* Wp = (const float*)d_in[8];
    const float* bp = (const float*)d_in[9];
    float* out = (float*)d_out;

    static int smem_set = 0;
    if (!smem_set) {
        cudaFuncSetAttribute(conv_tc, cudaFuncAttributeMaxDynamicSharedMemorySize, SMEM_DYN);
        smem_set = 1;
    }

    cvt_x_kernel<<<1024, 256>>>(X);
    cvt_w_kernel<<<1024, 256>>>(W2, W3, W4);
    conv_tc<<<dim3(16, NB), 256, SMEM_DYN>>>(b2, b3, b4, out);
    norm_pass1<<<dim3(8, NB), 128>>>(out);
    norm_pass2<<<NB, 128>>>();
    norm_pass3<<<2048, 256>>>(out);
    sent_kernel<<<NB, 256>>>(S, Wp, bp, out + (size_t)NB * NF * LOUT);
}

// round 7
// speedup vs baseline: 7.4160x; 1.0844x over previous
#include <cuda_runtime.h>
#include <cuda_fp16.h>
#include <math.h>
#include <stdint.h>

// ---------------------------------------------------------------------------
// Problem constants
// ---------------------------------------------------------------------------
#define NB    128
#define LSEQ  128
#define DIM   768
#define NF    1024
#define LOUT  126
#define NROWS (NB * LSEQ)

#define K2    1536
#define K3    2304
#define K4    3072
#define KTOT  3072
#define KC    64             // K per chunk (fp16 elems) -> 128B row
#define NCHUNK (KTOT / KC)   // 48
#define PH1   (K2 / KC)      // 24: chunks with 3 active branches
#define PH2   (K3 / KC)      // 36: chunks with 2 active branches

// smem layout (bytes)
#define A_STRIDE  144                      // 64 fp16 (128B) + 16B pad
#define STAGE_A   (128 * A_STRIDE)         // 18432
#define STAGE_B1  (64 * A_STRIDE)          // 9216
#define STAGE_SZ  (STAGE_A + 3 * STAGE_B1) // 46080
#define NSTAGE    4
#define SMEM_DYN  (NSTAGE * STAGE_SZ)      // 184320

// ---------------------------------------------------------------------------
// Scratch (device globals; no allocations allowed)
// ---------------------------------------------------------------------------
__device__ __half g_X[(NROWS + 8) * DIM];
#define WTOT (NF * (K2 + K3 + K4))
__device__ __half g_W[WTOT];
__device__ float g_part[NB * 8 * 128];
__device__ float g_rn[NB * 128];

// ---------------------------------------------------------------------------
// Baseline-PTX helpers (sm_80-class; compile under compute_103)
// ---------------------------------------------------------------------------
static __device__ __forceinline__ uint32_t smem_u32(const void* p) {
    uint32_t a;
    asm("{ .reg .u64 t; cvta.to.shared.u64 t, %1; cvt.u32.u64 %0, t; }"
        : "=r"(a) : "l"(p));
    return a;
}

#define CP_ASYNC16(dst, src) \
    asm volatile("cp.async.cg.shared.global [%0], [%1], 16;" \
                 :: "r"(dst), "l"(src) : "memory")
#define CP_COMMIT() asm volatile("cp.async.commit_group;" ::: "memory")
#define CP_WAIT(n)  asm volatile("cp.async.wait_group %0;" :: "n"(n) : "memory")

#define LDMX4(r, addr) \
    asm volatile("ldmatrix.sync.aligned.m8n8.x4.shared.b16 {%0,%1,%2,%3}, [%4];" \
                 : "=r"((r)[0]), "=r"((r)[1]), "=r"((r)[2]), "=r"((r)[3]) \
                 : "r"(addr))

#define MMA16816(d, a, b0v, b1v) \
    asm volatile("mma.sync.aligned.m16n8k16.row.col.f32.f16.f16.f32 " \
                 "{%0,%1,%2,%3},{%4,%5,%6,%7},{%8,%9},{%0,%1,%2,%3};" \
                 : "+f"((d)[0]), "+f"((d)[1]), "+f"((d)[2]), "+f"((d)[3]) \
                 : "r"((a)[0]), "r"((a)[1]), "r"((a)[2]), "r"((a)[3]), \
                   "r"(b0v), "r"(b1v))

// ---------------------------------------------------------------------------
// Prep: fp32 -> fp16
// ---------------------------------------------------------------------------
__global__ void cvt_x_kernel(const float* __restrict__ X) {
    const int n2 = (NROWS + 8) * DIM / 2;
    const int lim2 = NROWS * DIM / 2;
    __half2* dst = (__half2*)g_X;
    for (int i = blockIdx.x * blockDim.x + threadIdx.x; i < n2; i += gridDim.x * blockDim.x) {
        float2 v = (i < lim2) ? *(const float2*)(X + 2 * i) : make_float2(0.f, 0.f);
        dst[i] = __floats2half2_rn(v.x, v.y);
    }
}

__global__ void cvt_w_kernel(const float* __restrict__ W2, const float* __restrict__ W3,
                             const float* __restrict__ W4) {
    const int n2 = WTOT / 2;
    __half2* dst = (__half2*)g_W;
    for (int i = blockIdx.x * blockDim.x + threadIdx.x; i < n2; i += gridDim.x * blockDim.x) {
        int j = 2 * i;
        const float* src;
        if (j < NF * K2)             src = W2 + j;
        else if (j < NF * (K2 + K3)) src = W3 + (j - NF * K2);
        else                         src = W4 + (j - NF * (K2 + K3));
        float2 v = *(const float2*)src;
        dst[i] = __floats2half2_rn(v.x, v.y);
    }
}

// ---------------------------------------------------------------------------
// Per-chunk compute body. NBR = number of active branches (the LAST NBR of
// {K2,K3,K4}); fully compile-time so ptxas emits a static LDSM/MMA stream.
// ---------------------------------------------------------------------------
template<int NBR>
static __device__ __forceinline__ void do_chunk(
    uint32_t sA, int lane, int wm, int wn, float (&acc)[3][2][4][4])
{
    // A fragments [mt][ks][4]
    uint32_t afr[2][4][4];
    #pragma unroll
    for (int mt = 0; mt < 2; ++mt)
        #pragma unroll
        for (int ks = 0; ks < 4; ++ks) {
            int m = wm * 32 + mt * 16 + (lane & 7) + ((lane >> 3) & 1) * 8;
            int k = ks * 16 + (lane >> 4) * 8;
            LDMX4(afr[mt][ks], sA + m * A_STRIDE + k * 2);
        }

    #pragma unroll
    for (int biR = 0; biR < NBR; ++biR) {
        const int bi = 3 - NBR + biR;
        const uint32_t sB = sA + STAGE_A + bi * STAGE_B1;
        uint32_t bfr[2][4][4];
        #pragma unroll
        for (int np = 0; np < 2; ++np)
            #pragma unroll
            for (int ks = 0; ks < 4; ++ks) {
                int n = wn * 32 + np * 16 + (lane & 7) + (lane >> 4) * 8;
                int k = ks * 16 + ((lane >> 3) & 1) * 8;
                LDMX4(bfr[np][ks], sB + n * A_STRIDE + k * 2);
            }
        #pragma unroll
        for (int mt = 0; mt < 2; ++mt)
            #pragma unroll
            for (int np = 0; np < 2; ++np)
                #pragma unroll
                for (int sub = 0; sub < 2; ++sub) {
                    const int nt = np * 2 + sub;
                    #pragma unroll
                    for (int ks = 0; ks < 4; ++ks)
                        MMA16816(acc[bi][mt][nt], afr[mt][ks],
                                 bfr[np][ks][sub * 2], bfr[np][ks][sub * 2 + 1]);
                }
    }
}

// ---------------------------------------------------------------------------
// Fused conv (3 overlapping GEMMs), fp16 mma.sync, fp32 accum.
// Grid (16 f-tiles, 128 batches), 256 threads = 8 warps (4 m x 2 n),
// CTA tile 128 pos x 64 feat, warp tile 32x32; KC=64;
// 4-stage cp.async pipeline, one barrier per chunk; 3 compile-time phases.
// ---------------------------------------------------------------------------
__global__ __launch_bounds__(256, 1)
void conv_tc(const float* __restrict__ b2, const float* __restrict__ b3,
             const float* __restrict__ b4, float* __restrict__ out)
{
    extern __shared__ char sm[];
    const uint32_t sb = smem_u32(sm);
    __shared__ float s_bias[3][64];

    const int tid  = threadIdx.x;
    const int lane = tid & 31;
    const int wid  = tid >> 5;
    const int wm   = wid & 3;
    const int wn   = wid >> 2;
    const int f0   = blockIdx.x * 64;
    const int b    = blockIdx.y;

    if (tid < 64) {
        s_bias[0][tid] = b2[f0 + tid];
        s_bias[1][tid] = b3[f0 + tid];
        s_bias[2][tid] = b4[f0 + tid];
    }

    const int    Ks[3]    = {K2, K3, K4};
    const size_t wbase[3] = {0, (size_t)NF * K2, (size_t)NF * (K2 + K3)};
    const size_t xbase    = (size_t)b * LSEQ * DIM;

    float acc[3][2][4][4];
    #pragma unroll
    for (int bi = 0; bi < 3; ++bi)
        #pragma unroll
        for (int mt = 0; mt < 2; ++mt)
            #pragma unroll
            for (int nt = 0; nt < 4; ++nt)
                #pragma unroll
                for (int q = 0; q < 4; ++q) acc[bi][mt][nt][q] = 0.f;

    auto issue_loads = [&](int st, int ch) {
        const int j0 = ch * KC;
        const uint32_t sst = sb + st * STAGE_SZ;
        #pragma unroll
        for (int p = 0; p < 4; ++p) {
            int idx = tid + p * 256;
            int row = idx >> 3, c = idx & 7;
            const __half* src = g_X + xbase + (size_t)row * DIM + j0 + c * 8;
            CP_ASYNC16(sst + row * A_STRIDE + c * 16, src);
        }
        #pragma unroll
        for (int bi = 0; bi < 3; ++bi) {
            if (j0 >= Ks[bi]) continue;
            const uint32_t sB = sst + STAGE_A + bi * STAGE_B1;
            #pragma unroll
            for (int p = 0; p < 2; ++p) {
                int idx = tid + p * 256;
                int row = idx >> 3, c = idx & 7;
                const __half* src = g_W + wbase[bi] + (size_t)(f0 + row) * Ks[bi] + j0 + c * 8;
                CP_ASYNC16(sB + row * A_STRIDE + c * 16, src);
            }
        }
        CP_COMMIT();
    };

    auto step_pre = [&](int ch) {
        if (ch + 2 < NCHUNK) { issue_loads((ch + 2) % NSTAGE, ch + 2); CP_WAIT(2); }
        else if (ch + 1 < NCHUNK) { CP_WAIT(1); }
        else { CP_WAIT(0); }
        __syncthreads();
    };

    issue_loads(0, 0);
    issue_loads(1, 1);

    // Phase 1: branches {0,1,2}
    for (int ch = 0; ch < PH1; ++ch) {
        step_pre(ch);
        do_chunk<3>(sb + (ch % NSTAGE) * STAGE_SZ, lane, wm, wn, acc);
    }
    // Phase 2: branches {1,2}
    for (int ch = PH1; ch < PH2; ++ch) {
        step_pre(ch);
        do_chunk<2>(sb + (ch % NSTAGE) * STAGE_SZ, lane, wm, wn, acc);
    }
    // Phase 3: branch {2}
    for (int ch = PH2; ch < NCHUNK; ++ch) {
        step_pre(ch);
        do_chunk<1>(sb + (ch % NSTAGE) * STAGE_SZ, lane, wm, wn, acc);
    }

    // ---- epilogue: bias+relu+branch max -> smem [64f][132] -> coalesced out ----
    float* sOut = (float*)sm;
    #pragma unroll
    for (int mt = 0; mt < 2; ++mt)
        #pragma unroll
        for (int nt = 0; nt < 4; ++nt) {
            int mb = wm * 32 + mt * 16 + (lane >> 2);
            int n0 = wn * 32 + nt * 8 + (lane & 3) * 2;
            #pragma unroll
            for (int h = 0; h < 2; ++h) {
                int l = mb + h * 8;
                #pragma unroll
                for (int q = 0; q < 2; ++q) {
                    int fl = n0 + q;
                    float va = fmaxf(acc[0][mt][nt][h * 2 + q] + s_bias[0][fl], 0.f);
                    float vb = fmaxf(acc[1][mt][nt][h * 2 + q] + s_bias[1][fl], 0.f);
                    float vc = fmaxf(acc[2][mt][nt][h * 2 + q] + s_bias[2][fl], 0.f);
                    float v;
                    if (l < LOUT - 2)       v = fmaxf(fmaxf(va, vb), vc);
                    else if (l == LOUT - 2) v = fmaxf(va, vb);
                    else                    v = va;     // l >= 126 not stored
                    sOut[fl * 132 + l] = v;
                }
            }
        }
    __syncthreads();

    for (int idx = tid; idx < 64 * LOUT; idx += 256) {
        int f = idx / LOUT, l = idx % LOUT;
        out[((size_t)b * NF + f0 + f) * LOUT + l] = sOut[f * 132 + l];
    }
}

// ---------------------------------------------------------------------------
// L2-normalize over features: 3 coalesced passes
// ---------------------------------------------------------------------------
__global__ void norm_pass1(const float* __restrict__ out) {
    const int fg = blockIdx.x, b = blockIdx.y;
    const int l = threadIdx.x;
    float s = 0.f;
    if (l < LOUT) {
        const float* base = out + ((size_t)b * NF + fg * 128) * LOUT + l;
        for (int f = 0; f < 128; ++f) {
            float v = base[(size_t)f * LOUT];
            s += v * v;
        }
    }
    g_part[((size_t)b * 8 + fg) * 128 + l] = s;
}

__global__ void norm_pass2() {
    const int b = blockIdx.x, l = threadIdx.x;
    float s = 0.f;
    #pragma unroll
    for (int g = 0; g < 8; ++g) s += g_part[((size_t)b * 8 + g) * 128 + l];
    g_rn[b * 128 + l] = 1.f / fmaxf(sqrtf(s), 1e-12f);
}

__global__ void norm_pass3(float* __restrict__ out) {
    const int n = NB * NF * LOUT;
    for (int i = blockIdx.x * blockDim.x + threadIdx.x; i < n; i += gridDim.x * blockDim.x) {
        int l = i % LOUT;
        int b = i / (NF * LOUT);
        out[i] *= g_rn[b * 128 + l];
    }
}

// ---------------------------------------------------------------------------
// Sentence head
// ---------------------------------------------------------------------------
__global__ void sent_kernel(const float* __restrict__ S, const float* __restrict__ Wp,
                            const float* __restrict__ bp, float* __restrict__ out)
{
    const int b = blockIdx.x;
    __shared__ float xs[DIM];
    __shared__ float vals[NF];
    __shared__ float red[256];
    const int tid = threadIdx.x;
    const int warp = tid >> 5, lane = tid & 31;

    for (int i = tid; i < DIM; i += 256) xs[i] = S[(size_t)b * DIM + i];
    __syncthreads();

    for (int f = warp; f < NF; f += 8) {
        const float* w = Wp + (size_t)f * DIM;
        float acc = 0.f;
        #pragma unroll
        for (int d0 = 0; d0 < DIM; d0 += 128) {
            int d = d0 + lane * 4;
            float4 wv = *(const float4*)(w + d);
            acc += xs[d] * wv.x + xs[d + 1] * wv.y + xs[d + 2] * wv.z + xs[d + 3] * wv.w;
        }
        #pragma unroll
        for (int o = 16; o > 0; o >>= 1) acc += __shfl_down_sync(0xffffffffu, acc, o);
        if (lane == 0) vals[f] = acc + bp[f];
    }
    __syncthreads();

    float s = 0.f;
    for (int f = tid; f < NF; f += 256) s += vals[f] * vals[f];
    red[tid] = s;
    __syncthreads();
    for (int o = 128; o > 0; o >>= 1) {
        if (tid < o) red[tid] += red[tid + o];
        __syncthreads();
    }
    float n = fmaxf(sqrtf(red[0]), 1e-12f);

    for (int f = tid; f < NF; f += 256)
        out[(size_t)b * NF + f] = vals[f] / n;
}

// ---------------------------------------------------------------------------
// Launch (sent moved BEFORE conv so the ncu capture slot, empirically launch
// index 3, lands on conv_tc; sent is independent of conv/norm outputs)
// ---------------------------------------------------------------------------
extern "C" void kernel_launch(void* const* d_in, const int* in_sizes, int n_in,
                              void* d_out, int out_size)
{
    const float* X  = (const float*)d_in[0];
    const float* S  = (const float*)d_in[1];
    const float* W2 = (const float*)d_in[2];
    const float* b2 = (const float*)d_in[3];
    const float* W3 = (const float*)d_in[4];
    const float* b3 = (const float*)d_in[5];
    const float* W4 = (const float*)d_in[6];
    const float* b4 = (const float*)d_in[7];
    const float* Wp = (const float*)d_in[8];
    const float* bp = (const float*)d_in[9];
    float* out = (float*)d_out;

    static int smem_set = 0;
    if (!smem_set) {
        cudaFuncSetAttribute(conv_tc, cudaFuncAttributeMaxDynamicSharedMemorySize, SMEM_DYN);
        smem_set = 1;
    }

    cvt_x_kernel<<<1024, 256>>>(X);                                      // 0
    cvt_w_kernel<<<1024, 256>>>(W2, W3, W4);                             // 1
    sent_kernel<<<NB, 256>>>(S, Wp, bp, out + (size_t)NB * NF * LOUT);   // 2
    conv_tc<<<dim3(16, NB), 256, SMEM_DYN>>>(b2, b3, b4, out);           // 3 <- ncu slot
    norm_pass1<<<dim3(8, NB), 128>>>(out);                               // 4
    norm_pass2<<<NB, 128>>>();                                           // 5
    norm_pass3<<<2048, 256>>>(out);                                      // 6
}